// round 8
// baseline (speedup 1.0000x reference)
#include <cuda_runtime.h>

typedef unsigned long long ull;

// Problem constants
#define B_   4
#define C_   128
#define H_   64
#define W_   64
#define O_   128
#define KS_  7
#define PAD_ 3
#define HW_  (H_ * W_)

// Padded K/V layout: [b][c][70 rows][72 cols], valid region rows 3..66, cols 3..66.
#define PROWS_ 70
#define PCOLS_ 72
#define CHP_   (PROWS_ * PCOLS_)   // 5040

// Scratch (no allocs allowed)
__device__ float g_q [B_ * O_ * HW_];
__device__ float g_kp[B_ * O_ * CHP_];
__device__ float g_vp[B_ * O_ * CHP_];

// ---------------- packed f32x2 helpers ----------------
__device__ __forceinline__ ull fma2(ull a, ull b, ull c) {
    ull d;
    asm("fma.rn.f32x2 %0, %1, %2, %3;" : "=l"(d) : "l"(a), "l"(b), "l"(c));
    return d;
}
__device__ __forceinline__ ull add2(ull a, ull b) {
    ull d;
    asm("add.rn.f32x2 %0, %1, %2;" : "=l"(d) : "l"(a), "l"(b));
    return d;
}
__device__ __forceinline__ ull mul2(ull a, ull b) {
    ull d;
    asm("mul.rn.f32x2 %0, %1, %2;" : "=l"(d) : "l"(a), "l"(b));
    return d;
}
__device__ __forceinline__ ull pack2(float lo, float hi) {
    ull d;
    asm("mov.b64 %0, {%1, %2};" : "=l"(d) : "f"(lo), "f"(hi));
    return d;
}
__device__ __forceinline__ float2 unpack2(ull u) {
    float2 f;
    asm("mov.b64 {%0, %1}, %2;" : "=f"(f.x), "=f"(f.y) : "l"(u));
    return f;
}
// (hi of a, lo of b)
__device__ __forceinline__ ull mix_hl(ull a, ull b) {
    ull d;
    asm("{\n\t"
        ".reg .b32 al, ah, bl, bh;\n\t"
        "mov.b64 {al, ah}, %1;\n\t"
        "mov.b64 {bl, bh}, %2;\n\t"
        "mov.b64 %0, {ah, bl};\n\t"
        "}" : "=l"(d) : "l"(a), "l"(b));
    return d;
}

// ---------------- zero the pad cells of g_kp / g_vp ----------------
// One thread per (buffer, channel, row): 2 * 512 * 70 = 71680 threads.
__global__ void zero_pads() {
    int idx = blockIdx.x * 256 + threadIdx.x;
    const int per_buf = B_ * O_ * PROWS_;   // 35840
    if (idx >= 2 * per_buf) return;
    float* buf = (idx < per_buf) ? g_kp : g_vp;
    int r   = (idx < per_buf) ? idx : idx - per_buf;
    int ch  = r / PROWS_;
    int row = r - ch * PROWS_;
    float* p = buf + (size_t)ch * CHP_ + row * PCOLS_;
    if (row < PAD_ || row > 66) {
        #pragma unroll
        for (int i = 0; i < PCOLS_ / 4; i++)
            reinterpret_cast<float4*>(p)[i] = make_float4(0.f, 0.f, 0.f, 0.f);
    } else {
        p[0] = 0.f; p[1] = 0.f; p[2] = 0.f;
        p[67] = 0.f; p[68] = 0.f; p[69] = 0.f; p[70] = 0.f; p[71] = 0.f;
    }
}

// ---------------- QKV projection: Out[o,n] = sum_c W[o,c] * X[c,n] ----------------
// grid: (32 col-tiles of 128 pixels, 3 = q/k/v, 4 = batch), 256 threads.
// Tile 128(O) x 128(N), BK=16, per-thread 8(O) x 8(N) with cols at 32j + 2tc
// (conflict-free LDS.64 on the B fragment).
__global__ __launch_bounds__(256) void qkv_gemm(
    const float* __restrict__ x,
    const float* __restrict__ wq,
    const float* __restrict__ wk,
    const float* __restrict__ wv)
{
    const int nTile = blockIdx.x * 128;
    const int which = blockIdx.y;
    const int b     = blockIdx.z;

    const float* Wt = (which == 0) ? wq : (which == 1) ? wk : wv;

    __shared__ float As[16][132];   // [k][o]
    __shared__ float Bs[16][132];   // [k][n]

    const int t  = threadIdx.x;
    const int tr = t >> 4;          // 0..15
    const int tc = t & 15;          // 0..15

    ull acc2[8][4];
    #pragma unroll
    for (int i = 0; i < 8; i++)
        #pragma unroll
        for (int j = 0; j < 4; j++) acc2[i][j] = 0ull;

    const float* Xb = x + (size_t)b * C_ * HW_ + nTile;

    for (int k0 = 0; k0 < C_; k0 += 16) {
        #pragma unroll
        for (int i = 0; i < 2; i++) {
            int f   = t + i * 256;
            int row = f >> 2;
            int cv  = f & 3;
            float4 a = *reinterpret_cast<const float4*>(&Wt[row * C_ + k0 + cv * 4]);
            As[cv * 4 + 0][row] = a.x;
            As[cv * 4 + 1][row] = a.y;
            As[cv * 4 + 2][row] = a.z;
            As[cv * 4 + 3][row] = a.w;
        }
        #pragma unroll
        for (int i = 0; i < 2; i++) {
            int f   = t + i * 256;
            int row = f >> 5;
            int cv  = f & 31;
            float4 v = *reinterpret_cast<const float4*>(&Xb[(size_t)(k0 + row) * HW_ + cv * 4]);
            *reinterpret_cast<float4*>(&Bs[row][cv * 4]) = v;
        }
        __syncthreads();

        #pragma unroll
        for (int k = 0; k < 16; k++) {
            float a[8];
            #pragma unroll
            for (int i = 0; i < 8; i++) a[i] = As[k][tr * 8 + i];
            ull b2[4];
            #pragma unroll
            for (int j = 0; j < 4; j++)
                b2[j] = *reinterpret_cast<const ull*>(&Bs[k][32 * j + 2 * tc]);
            #pragma unroll
            for (int i = 0; i < 8; i++) {
                ull aa = pack2(a[i], a[i]);
                #pragma unroll
                for (int j = 0; j < 4; j++)
                    acc2[i][j] = fma2(aa, b2[j], acc2[i][j]);
            }
        }
        __syncthreads();
    }

    if (which == 0) {
        float* Ob = g_q + (size_t)b * O_ * HW_ + nTile;
        #pragma unroll
        for (int i = 0; i < 8; i++) {
            int o = tr * 8 + i;
            #pragma unroll
            for (int j = 0; j < 4; j++) {
                float2 v = unpack2(acc2[i][j]);
                *reinterpret_cast<float2*>(&Ob[(size_t)o * HW_ + 32 * j + 2 * tc]) = v;
            }
        }
    } else {
        float* dst0 = (which == 1) ? g_kp : g_vp;
        #pragma unroll
        for (int i = 0; i < 8; i++) {
            int o = tr * 8 + i;
            float* base = dst0 + (size_t)(b * O_ + o) * CHP_;
            #pragma unroll
            for (int j = 0; j < 4; j++) {
                int p   = nTile + 32 * j + 2 * tc;
                int row = p >> 6;
                int col = p & 63;
                float2 v = unpack2(acc2[i][j]);
                float* d = base + (row + PAD_) * PCOLS_ + (col + PAD_);
                d[0] = v.x;
                d[1] = v.y;
            }
        }
    }
}

// ---------------- Attention ----------------
// Block = 128 threads = 16 pixel-pairs (half a row, 32 px) x 8 channel-lanes.
// Grid = (128 = 64 rows x 2 halves, 4 batches) = 512 blocks.
// Channels in 8 chunks of 16; lane ln owns channels {2ln, 2ln+1} of each chunk.
// Logits packed f32x2 over the pixel pair; lane reduce via 3x shfl_xor.
#define WS_ 290    // smem channel stride (>= 7*40, == 2 mod 16 for bank spread)

__device__ __forceinline__ void load_window(
    const float* __restrict__ src, int bc0, int h, int half, int t, float* sW)
{
    const float* base = src + (size_t)bc0 * CHP_ + (size_t)h * PCOLS_ + half * 32;
    #pragma unroll
    for (int i = 0; i < 9; i++) {
        int lin = t + i * 128;            // over 16ch * 7rows * 10 float4 = 1120
        if (lin < 1120) {
            int c   = lin / 70;
            int rem = lin - c * 70;
            int row = rem / 10;
            int c4  = rem - row * 10;
            float4 v = *reinterpret_cast<const float4*>(
                base + (size_t)c * CHP_ + row * PCOLS_ + c4 * 4);
            float* d = sW + c * WS_ + row * 40 + c4 * 4;
            *reinterpret_cast<float2*>(d)     = make_float2(v.x, v.y);
            *reinterpret_cast<float2*>(d + 2) = make_float2(v.z, v.w);
        }
    }
}

__global__ __launch_bounds__(128, 3) void attn_kernel(
    const float* __restrict__ rel_x,
    const float* __restrict__ rel_y,
    float* __restrict__ out)
{
    const int hb   = blockIdx.x;       // 0..127
    const int h    = hb >> 1;
    const int half = hb & 1;
    const int b    = blockIdx.y;
    const int t    = threadIdx.x;
    const int ln   = t & 7;            // channel lane
    const int pp   = t >> 3;           // pixel pair 0..15

    __shared__ float sW[16 * WS_];
    __shared__ float sQ[16][32];
    __shared__ float sR[16][7];

    if (t < 112) {
        int r = t / 7;
        sR[r][t - r * 7] = (r < 8) ? rel_x[t] : rel_y[t - 56];
    }

    ull logits[49];
    #pragma unroll
    for (int i = 0; i < 49; i++) logits[i] = 0ull;
    ull bias[7] = {0ull, 0ull, 0ull, 0ull, 0ull, 0ull, 0ull};

    const int cl0 = 2 * ln;            // local channels cl0, cl0+1

    // ---------------- Phase 1: logits + bias partials ----------------
    for (int cc = 0; cc < 8; cc++) {
        const int c0 = cc * 16;
        __syncthreads();
        load_window(g_kp, b * O_ + c0, h, half, t, sW);
        {
            int c = t >> 3, c4 = t & 7;
            *reinterpret_cast<float4*>(&sQ[c][c4 * 4]) =
                *reinterpret_cast<const float4*>(
                    &g_q[(size_t)(b * O_ + c0 + c) * HW_ + h * W_ + half * 32 + c4 * 4]);
        }
        __syncthreads();

        #pragma unroll
        for (int sub = 0; sub < 2; sub++) {
            const int c = cl0 + sub;
            const ull q2 = *reinterpret_cast<const ull*>(&sQ[c][2 * pp]);
            #pragma unroll
            for (int k = 0; k < 7; k++) {
                float rv = sR[c][k];
                bias[k] = fma2(q2, pack2(rv, rv), bias[k]);
            }
            const float* wp = &sW[c * WS_ + 2 * pp];
            #pragma unroll
            for (int ki = 0; ki < 7; ki++) {
                const ull* rp = reinterpret_cast<const ull*>(wp + ki * 40);
                ull v0 = rp[0], v1 = rp[1], v2 = rp[2], v3 = rp[3];
                ull p1 = mix_hl(v0, v1);
                ull p3 = mix_hl(v1, v2);
                ull p5 = mix_hl(v2, v3);
                logits[ki * 7 + 0] = fma2(q2, v0, logits[ki * 7 + 0]);
                logits[ki * 7 + 1] = fma2(q2, p1, logits[ki * 7 + 1]);
                logits[ki * 7 + 2] = fma2(q2, v1, logits[ki * 7 + 2]);
                logits[ki * 7 + 3] = fma2(q2, p3, logits[ki * 7 + 3]);
                logits[ki * 7 + 4] = fma2(q2, v2, logits[ki * 7 + 4]);
                logits[ki * 7 + 5] = fma2(q2, p5, logits[ki * 7 + 5]);
                logits[ki * 7 + 6] = fma2(q2, v3, logits[ki * 7 + 6]);
            }
        }
    }

    // Fold bias partials into logits pre-reduction: lanes 0..3 hold bias_x
    // partials (index kj), lanes 4..7 hold bias_y partials (index ki). The
    // lane reduction then yields logits + bias_x[kj] + bias_y[ki].
    if (ln < 4) {
        #pragma unroll
        for (int ki = 0; ki < 7; ki++)
            #pragma unroll
            for (int kj = 0; kj < 7; kj++)
                logits[ki * 7 + kj] = add2(logits[ki * 7 + kj], bias[kj]);
    } else {
        #pragma unroll
        for (int ki = 0; ki < 7; ki++)
            #pragma unroll
            for (int kj = 0; kj < 7; kj++)
                logits[ki * 7 + kj] = add2(logits[ki * 7 + kj], bias[ki]);
    }

    // Reduce over the 8 channel lanes (warp lane bits 0..2).
    const unsigned mask = 0xFFFFFFFFu;
    #pragma unroll
    for (int i = 0; i < 49; i++) {
        ull v = logits[i];
        v = add2(v, __shfl_xor_sync(mask, v, 1));
        v = add2(v, __shfl_xor_sync(mask, v, 2));
        v = add2(v, __shfl_xor_sync(mask, v, 4));
        logits[i] = v;
    }

    // ---------------- Softmax (both pixels of the pair) ----------------
    float m0 = -3.0e38f, m1 = -3.0e38f;
    #pragma unroll
    for (int i = 0; i < 49; i++) {
        float2 f = unpack2(logits[i]);
        m0 = fmaxf(m0, f.x);
        m1 = fmaxf(m1, f.y);
    }
    float s0 = 0.f, s1 = 0.f;
    #pragma unroll
    for (int i = 0; i < 49; i++) {
        float2 f = unpack2(logits[i]);
        float e0 = __expf(f.x - m0);
        float e1 = __expf(f.y - m1);
        s0 += e0; s1 += e1;
        logits[i] = pack2(e0, e1);
    }
    const ull inv2 = pack2(1.f / s0, 1.f / s1);
    #pragma unroll
    for (int i = 0; i < 49; i++) logits[i] = mul2(logits[i], inv2);

    // ---------------- Phase 2: out = attn . v_window ----------------
    for (int cc = 0; cc < 8; cc++) {
        const int c0 = cc * 16;
        __syncthreads();
        load_window(g_vp, b * O_ + c0, h, half, t, sW);
        __syncthreads();

        #pragma unroll
        for (int sub = 0; sub < 2; sub++) {
            const int c = cl0 + sub;
            ull acc = 0ull;
            const float* wp = &sW[c * WS_ + 2 * pp];
            #pragma unroll
            for (int ki = 0; ki < 7; ki++) {
                const ull* rp = reinterpret_cast<const ull*>(wp + ki * 40);
                ull v0 = rp[0], v1 = rp[1], v2 = rp[2], v3 = rp[3];
                ull p1 = mix_hl(v0, v1);
                ull p3 = mix_hl(v1, v2);
                ull p5 = mix_hl(v2, v3);
                acc = fma2(logits[ki * 7 + 0], v0, acc);
                acc = fma2(logits[ki * 7 + 1], p1, acc);
                acc = fma2(logits[ki * 7 + 2], v1, acc);
                acc = fma2(logits[ki * 7 + 3], p3, acc);
                acc = fma2(logits[ki * 7 + 4], v2, acc);
                acc = fma2(logits[ki * 7 + 5], p5, acc);
                acc = fma2(logits[ki * 7 + 6], v3, acc);
            }
            float2 r = unpack2(acc);
            *reinterpret_cast<float2*>(
                &out[(size_t)(b * O_ + c0 + c) * HW_ + h * W_ + half * 32 + 2 * pp]) = r;
        }
    }
}

// ---------------- launch ----------------
extern "C" void kernel_launch(void* const* d_in, const int* in_sizes, int n_in,
                              void* d_out, int out_size) {
    (void)in_sizes; (void)n_in; (void)out_size;
    const float* x     = (const float*)d_in[0];
    const float* wq    = (const float*)d_in[1];
    const float* wk    = (const float*)d_in[2];
    const float* wv    = (const float*)d_in[3];
    const float* rel_x = (const float*)d_in[4];
    const float* rel_y = (const float*)d_in[5];
    float* out = (float*)d_out;

    zero_pads<<<(2 * B_ * O_ * PROWS_ + 255) / 256, 256>>>();
    qkv_gemm<<<dim3(32, 3, 4), 256>>>(x, wq, wk, wv);
    attn_kernel<<<dim3(128, 4), 128>>>(rel_x, rel_y, out);
}

// round 11
// speedup vs baseline: 1.0147x; 1.0147x over previous
#include <cuda_runtime.h>

typedef unsigned long long ull;

// Problem constants
#define B_   4
#define C_   128
#define H_   64
#define W_   64
#define O_   128
#define KS_  7
#define PAD_ 3
#define HW_  (H_ * W_)

// Padded K/V layout: [b][c][70 rows][72 cols], valid region rows 3..66, cols 3..66.
#define PROWS_ 70
#define PCOLS_ 72
#define CHP_   (PROWS_ * PCOLS_)   // 5040

// Scratch (no allocs allowed)
__device__ float g_q [B_ * O_ * HW_];
__device__ float g_kp[B_ * O_ * CHP_];
__device__ float g_vp[B_ * O_ * CHP_];

// ---------------- packed f32x2 helpers ----------------
__device__ __forceinline__ ull fma2(ull a, ull b, ull c) {
    ull d;
    asm("fma.rn.f32x2 %0, %1, %2, %3;" : "=l"(d) : "l"(a), "l"(b), "l"(c));
    return d;
}
__device__ __forceinline__ ull add2(ull a, ull b) {
    ull d;
    asm("add.rn.f32x2 %0, %1, %2;" : "=l"(d) : "l"(a), "l"(b));
    return d;
}
__device__ __forceinline__ ull mul2(ull a, ull b) {
    ull d;
    asm("mul.rn.f32x2 %0, %1, %2;" : "=l"(d) : "l"(a), "l"(b));
    return d;
}
__device__ __forceinline__ ull pack2(float lo, float hi) {
    ull d;
    asm("mov.b64 %0, {%1, %2};" : "=l"(d) : "f"(lo), "f"(hi));
    return d;
}
__device__ __forceinline__ float2 unpack2(ull u) {
    float2 f;
    asm("mov.b64 {%0, %1}, %2;" : "=f"(f.x), "=f"(f.y) : "l"(u));
    return f;
}
// (hi of a, lo of b)
__device__ __forceinline__ ull mix_hl(ull a, ull b) {
    ull d;
    asm("{\n\t"
        ".reg .b32 al, ah, bl, bh;\n\t"
        "mov.b64 {al, ah}, %1;\n\t"
        "mov.b64 {bl, bh}, %2;\n\t"
        "mov.b64 %0, {ah, bl};\n\t"
        "}" : "=l"(d) : "l"(a), "l"(b));
    return d;
}

// ---------------- zero the pad cells of g_kp / g_vp ----------------
// One thread per (buffer, channel, row): 2 * 512 * 70 = 71680 threads.
__global__ void zero_pads() {
    int idx = blockIdx.x * 256 + threadIdx.x;
    const int per_buf = B_ * O_ * PROWS_;   // 35840
    if (idx >= 2 * per_buf) return;
    float* buf = (idx < per_buf) ? g_kp : g_vp;
    int r   = (idx < per_buf) ? idx : idx - per_buf;
    int ch  = r / PROWS_;
    int row = r - ch * PROWS_;
    float* p = buf + (size_t)ch * CHP_ + row * PCOLS_;
    if (row < PAD_ || row > 66) {
        #pragma unroll
        for (int i = 0; i < PCOLS_ / 4; i++)
            reinterpret_cast<float4*>(p)[i] = make_float4(0.f, 0.f, 0.f, 0.f);
    } else {
        p[0] = 0.f; p[1] = 0.f; p[2] = 0.f;
        p[67] = 0.f; p[68] = 0.f; p[69] = 0.f; p[70] = 0.f; p[71] = 0.f;
    }
}

// ---------------- QKV projection: Out[o,n] = sum_c W[o,c] * X[c,n] ----------------
// grid: (32 col-tiles of 128 pixels, 3 = q/k/v, 4 = batch), 256 threads.
// Tile 128(O) x 128(N), BK=16, per-thread 8(O) x 8(N) with cols at 32j + 2tc
// (conflict-free LDS.64 on the B fragment).
__global__ __launch_bounds__(256) void qkv_gemm(
    const float* __restrict__ x,
    const float* __restrict__ wq,
    const float* __restrict__ wk,
    const float* __restrict__ wv)
{
    const int nTile = blockIdx.x * 128;
    const int which = blockIdx.y;
    const int b     = blockIdx.z;

    const float* Wt = (which == 0) ? wq : (which == 1) ? wk : wv;

    __shared__ float As[16][132];   // [k][o]
    __shared__ float Bs[16][132];   // [k][n]

    const int t  = threadIdx.x;
    const int tr = t >> 4;          // 0..15
    const int tc = t & 15;          // 0..15

    ull acc2[8][4];
    #pragma unroll
    for (int i = 0; i < 8; i++)
        #pragma unroll
        for (int j = 0; j < 4; j++) acc2[i][j] = 0ull;

    const float* Xb = x + (size_t)b * C_ * HW_ + nTile;

    for (int k0 = 0; k0 < C_; k0 += 16) {
        #pragma unroll
        for (int i = 0; i < 2; i++) {
            int f   = t + i * 256;
            int row = f >> 2;
            int cv  = f & 3;
            float4 a = *reinterpret_cast<const float4*>(&Wt[row * C_ + k0 + cv * 4]);
            As[cv * 4 + 0][row] = a.x;
            As[cv * 4 + 1][row] = a.y;
            As[cv * 4 + 2][row] = a.z;
            As[cv * 4 + 3][row] = a.w;
        }
        #pragma unroll
        for (int i = 0; i < 2; i++) {
            int f   = t + i * 256;
            int row = f >> 5;
            int cv  = f & 31;
            float4 v = *reinterpret_cast<const float4*>(&Xb[(size_t)(k0 + row) * HW_ + cv * 4]);
            *reinterpret_cast<float4*>(&Bs[row][cv * 4]) = v;
        }
        __syncthreads();

        #pragma unroll
        for (int k = 0; k < 16; k++) {
            float a[8];
            #pragma unroll
            for (int i = 0; i < 8; i++) a[i] = As[k][tr * 8 + i];
            ull b2[4];
            #pragma unroll
            for (int j = 0; j < 4; j++)
                b2[j] = *reinterpret_cast<const ull*>(&Bs[k][32 * j + 2 * tc]);
            #pragma unroll
            for (int i = 0; i < 8; i++) {
                ull aa = pack2(a[i], a[i]);
                #pragma unroll
                for (int j = 0; j < 4; j++)
                    acc2[i][j] = fma2(aa, b2[j], acc2[i][j]);
            }
        }
        __syncthreads();
    }

    if (which == 0) {
        float* Ob = g_q + (size_t)b * O_ * HW_ + nTile;
        #pragma unroll
        for (int i = 0; i < 8; i++) {
            int o = tr * 8 + i;
            #pragma unroll
            for (int j = 0; j < 4; j++) {
                float2 v = unpack2(acc2[i][j]);
                *reinterpret_cast<float2*>(&Ob[(size_t)o * HW_ + 32 * j + 2 * tc]) = v;
            }
        }
    } else {
        float* dst0 = (which == 1) ? g_kp : g_vp;
        #pragma unroll
        for (int i = 0; i < 8; i++) {
            int o = tr * 8 + i;
            float* base = dst0 + (size_t)(b * O_ + o) * CHP_;
            #pragma unroll
            for (int j = 0; j < 4; j++) {
                int p   = nTile + 32 * j + 2 * tc;
                int row = p >> 6;
                int col = p & 63;
                float2 v = unpack2(acc2[i][j]);
                float* d = base + (row + PAD_) * PCOLS_ + (col + PAD_);
                d[0] = v.x;
                d[1] = v.y;
            }
        }
    }
}

// ---------------- Attention ----------------
// Block = 128 threads = 16 pixel-pairs (half a row, 32 px) x 8 channel-lanes.
// Grid = (128 = 64 rows x 2 halves, 4 batches) = 512 blocks.
// Channels in 8 chunks of 16; lane ln owns channels {2ln, 2ln+1} of each chunk.
// Logits packed f32x2 over the pixel pair; lane reduce via 3x shfl_xor.
#define WS_ 290    // smem channel stride (>= 7*40, == 2 mod 16 for bank spread)

__device__ __forceinline__ void load_window(
    const float* __restrict__ src, int bc0, int h, int half, int t, float* sW)
{
    const float* base = src + (size_t)bc0 * CHP_ + (size_t)h * PCOLS_ + half * 32;
    #pragma unroll
    for (int i = 0; i < 9; i++) {
        int lin = t + i * 128;            // over 16ch * 7rows * 10 float4 = 1120
        if (lin < 1120) {
            int c   = lin / 70;
            int rem = lin - c * 70;
            int row = rem / 10;
            int c4  = rem - row * 10;
            float4 v = *reinterpret_cast<const float4*>(
                base + (size_t)c * CHP_ + row * PCOLS_ + c4 * 4);
            float* d = sW + c * WS_ + row * 40 + c4 * 4;
            *reinterpret_cast<float2*>(d)     = make_float2(v.x, v.y);
            *reinterpret_cast<float2*>(d + 2) = make_float2(v.z, v.w);
        }
    }
}

__global__ __launch_bounds__(128, 3) void attn_kernel(
    const float* __restrict__ rel_x,
    const float* __restrict__ rel_y,
    float* __restrict__ out)
{
    const int hb   = blockIdx.x;       // 0..127
    const int h    = hb >> 1;
    const int half = hb & 1;
    const int b    = blockIdx.y;
    const int t    = threadIdx.x;
    const int ln   = t & 7;            // channel lane
    const int pp   = t >> 3;           // pixel pair 0..15

    __shared__ float sW[16 * WS_];
    __shared__ float sQ[16][32];
    __shared__ float sR[16][7];

    if (t < 112) {
        int r = t / 7;
        sR[r][t - r * 7] = (r < 8) ? rel_x[t] : rel_y[t - 56];
    }

    ull logits[49];
    #pragma unroll
    for (int i = 0; i < 49; i++) logits[i] = 0ull;
    ull bias[7] = {0ull, 0ull, 0ull, 0ull, 0ull, 0ull, 0ull};

    const int cl0 = 2 * ln;            // local channels cl0, cl0+1

    // ---------------- Phase 1: logits + bias partials ----------------
    for (int cc = 0; cc < 8; cc++) {
        const int c0 = cc * 16;
        __syncthreads();
        load_window(g_kp, b * O_ + c0, h, half, t, sW);
        {
            int c = t >> 3, c4 = t & 7;
            *reinterpret_cast<float4*>(&sQ[c][c4 * 4]) =
                *reinterpret_cast<const float4*>(
                    &g_q[(size_t)(b * O_ + c0 + c) * HW_ + h * W_ + half * 32 + c4 * 4]);
        }
        __syncthreads();

        #pragma unroll
        for (int sub = 0; sub < 2; sub++) {
            const int c = cl0 + sub;
            const ull q2 = *reinterpret_cast<const ull*>(&sQ[c][2 * pp]);
            #pragma unroll
            for (int k = 0; k < 7; k++) {
                float rv = sR[c][k];
                bias[k] = fma2(q2, pack2(rv, rv), bias[k]);
            }
            const float* wp = &sW[c * WS_ + 2 * pp];
            #pragma unroll
            for (int ki = 0; ki < 7; ki++) {
                const ull* rp = reinterpret_cast<const ull*>(wp + ki * 40);
                ull v0 = rp[0], v1 = rp[1], v2 = rp[2], v3 = rp[3];
                ull p1 = mix_hl(v0, v1);
                ull p3 = mix_hl(v1, v2);
                ull p5 = mix_hl(v2, v3);
                logits[ki * 7 + 0] = fma2(q2, v0, logits[ki * 7 + 0]);
                logits[ki * 7 + 1] = fma2(q2, p1, logits[ki * 7 + 1]);
                logits[ki * 7 + 2] = fma2(q2, v1, logits[ki * 7 + 2]);
                logits[ki * 7 + 3] = fma2(q2, p3, logits[ki * 7 + 3]);
                logits[ki * 7 + 4] = fma2(q2, v2, logits[ki * 7 + 4]);
                logits[ki * 7 + 5] = fma2(q2, p5, logits[ki * 7 + 5]);
                logits[ki * 7 + 6] = fma2(q2, v3, logits[ki * 7 + 6]);
            }
        }
    }

    // Fold bias partials into logits pre-reduction: lanes 0..3 hold bias_x
    // partials (index kj), lanes 4..7 hold bias_y partials (index ki). The
    // lane reduction then yields logits + bias_x[kj] + bias_y[ki].
    if (ln < 4) {
        #pragma unroll
        for (int ki = 0; ki < 7; ki++)
            #pragma unroll
            for (int kj = 0; kj < 7; kj++)
                logits[ki * 7 + kj] = add2(logits[ki * 7 + kj], bias[kj]);
    } else {
        #pragma unroll
        for (int ki = 0; ki < 7; ki++)
            #pragma unroll
            for (int kj = 0; kj < 7; kj++)
                logits[ki * 7 + kj] = add2(logits[ki * 7 + kj], bias[ki]);
    }

    // Reduce over the 8 channel lanes (warp lane bits 0..2).
    const unsigned mask = 0xFFFFFFFFu;
    #pragma unroll
    for (int i = 0; i < 49; i++) {
        ull v = logits[i];
        v = add2(v, __shfl_xor_sync(mask, v, 1));
        v = add2(v, __shfl_xor_sync(mask, v, 2));
        v = add2(v, __shfl_xor_sync(mask, v, 4));
        logits[i] = v;
    }

    // ---------------- Softmax (both pixels of the pair) ----------------
    float m0 = -3.0e38f, m1 = -3.0e38f;
    #pragma unroll
    for (int i = 0; i < 49; i++) {
        float2 f = unpack2(logits[i]);
        m0 = fmaxf(m0, f.x);
        m1 = fmaxf(m1, f.y);
    }
    float s0 = 0.f, s1 = 0.f;
    #pragma unroll
    for (int i = 0; i < 49; i++) {
        float2 f = unpack2(logits[i]);
        float e0 = __expf(f.x - m0);
        float e1 = __expf(f.y - m1);
        s0 += e0; s1 += e1;
        logits[i] = pack2(e0, e1);
    }
    const ull inv2 = pack2(1.f / s0, 1.f / s1);
    #pragma unroll
    for (int i = 0; i < 49; i++) logits[i] = mul2(logits[i], inv2);

    // ---------------- Phase 2: out = attn . v_window ----------------
    for (int cc = 0; cc < 8; cc++) {
        const int c0 = cc * 16;
        __syncthreads();
        load_window(g_vp, b * O_ + c0, h, half, t, sW);
        __syncthreads();

        #pragma unroll
        for (int sub = 0; sub < 2; sub++) {
            const int c = cl0 + sub;
            ull acc = 0ull;
            const float* wp = &sW[c * WS_ + 2 * pp];
            #pragma unroll
            for (int ki = 0; ki < 7; ki++) {
                const ull* rp = reinterpret_cast<const ull*>(wp + ki * 40);
                ull v0 = rp[0], v1 = rp[1], v2 = rp[2], v3 = rp[3];
                ull p1 = mix_hl(v0, v1);
                ull p3 = mix_hl(v1, v2);
                ull p5 = mix_hl(v2, v3);
                acc = fma2(logits[ki * 7 + 0], v0, acc);
                acc = fma2(logits[ki * 7 + 1], p1, acc);
                acc = fma2(logits[ki * 7 + 2], v1, acc);
                acc = fma2(logits[ki * 7 + 3], p3, acc);
                acc = fma2(logits[ki * 7 + 4], v2, acc);
                acc = fma2(logits[ki * 7 + 5], p5, acc);
                acc = fma2(logits[ki * 7 + 6], v3, acc);
            }
            float2 r = unpack2(acc);
            *reinterpret_cast<float2*>(
                &out[(size_t)(b * O_ + c0 + c) * HW_ + h * W_ + half * 32 + 2 * pp]) = r;
        }
    }
}

// ---------------- launch ----------------
extern "C" void kernel_launch(void* const* d_in, const int* in_sizes, int n_in,
                              void* d_out, int out_size) {
    (void)in_sizes; (void)n_in; (void)out_size;
    const float* x     = (const float*)d_in[0];
    const float* wq    = (const float*)d_in[1];
    const float* wk    = (const float*)d_in[2];
    const float* wv    = (const float*)d_in[3];
    const float* rel_x = (const float*)d_in[4];
    const float* rel_y = (const float*)d_in[5];
    float* out = (float*)d_out;

    zero_pads<<<(2 * B_ * O_ * PROWS_ + 255) / 256, 256>>>();
    qkv_gemm<<<dim3(32, 3, 4), 256>>>(x, wq, wk, wv);
    attn_kernel<<<dim3(128, 4), 128>>>(rel_x, rel_y, out);
}

// round 15
// speedup vs baseline: 1.0311x; 1.0162x over previous
#include <cuda_runtime.h>

typedef unsigned long long ull;

// Problem constants
#define B_   4
#define C_   128
#define H_   64
#define W_   64
#define O_   128
#define KS_  7
#define PAD_ 3
#define HW_  (H_ * W_)

// Padded K/V layout: [b][c][70 rows][72 cols], valid region rows 3..66, cols 3..66.
#define PROWS_ 70
#define PCOLS_ 72
#define CHP_   (PROWS_ * PCOLS_)   // 5040

// Scratch (no allocs allowed)
__device__ float g_q [B_ * O_ * HW_];
__device__ float g_kp[B_ * O_ * CHP_];
__device__ float g_vp[B_ * O_ * CHP_];

// ---------------- packed f32x2 helpers ----------------
__device__ __forceinline__ ull fma2(ull a, ull b, ull c) {
    ull d;
    asm("fma.rn.f32x2 %0, %1, %2, %3;" : "=l"(d) : "l"(a), "l"(b), "l"(c));
    return d;
}
__device__ __forceinline__ ull add2(ull a, ull b) {
    ull d;
    asm("add.rn.f32x2 %0, %1, %2;" : "=l"(d) : "l"(a), "l"(b));
    return d;
}
__device__ __forceinline__ ull mul2(ull a, ull b) {
    ull d;
    asm("mul.rn.f32x2 %0, %1, %2;" : "=l"(d) : "l"(a), "l"(b));
    return d;
}
__device__ __forceinline__ ull pack2(float lo, float hi) {
    ull d;
    asm("mov.b64 %0, {%1, %2};" : "=l"(d) : "f"(lo), "f"(hi));
    return d;
}
__device__ __forceinline__ float2 unpack2(ull u) {
    float2 f;
    asm("mov.b64 {%0, %1}, %2;" : "=f"(f.x), "=f"(f.y) : "l"(u));
    return f;
}
// (hi of a, lo of b)
__device__ __forceinline__ ull mix_hl(ull a, ull b) {
    ull d;
    asm("{\n\t"
        ".reg .b32 al, ah, bl, bh;\n\t"
        "mov.b64 {al, ah}, %1;\n\t"
        "mov.b64 {bl, bh}, %2;\n\t"
        "mov.b64 %0, {ah, bl};\n\t"
        "}" : "=l"(d) : "l"(a), "l"(b));
    return d;
}

// ---------------- zero the pad cells of g_kp / g_vp ----------------
// One thread per (buffer, channel, row): 2 * 512 * 70 = 71680 threads.
__global__ void zero_pads() {
    int idx = blockIdx.x * 256 + threadIdx.x;
    const int per_buf = B_ * O_ * PROWS_;   // 35840
    if (idx >= 2 * per_buf) return;
    float* buf = (idx < per_buf) ? g_kp : g_vp;
    int r   = (idx < per_buf) ? idx : idx - per_buf;
    int ch  = r / PROWS_;
    int row = r - ch * PROWS_;
    float* p = buf + (size_t)ch * CHP_ + row * PCOLS_;
    if (row < PAD_ || row > 66) {
        #pragma unroll
        for (int i = 0; i < PCOLS_ / 4; i++)
            reinterpret_cast<float4*>(p)[i] = make_float4(0.f, 0.f, 0.f, 0.f);
    } else {
        p[0] = 0.f; p[1] = 0.f; p[2] = 0.f;
        p[67] = 0.f; p[68] = 0.f; p[69] = 0.f; p[70] = 0.f; p[71] = 0.f;
    }
}

// ---------------- QKV projection: Out[o,n] = sum_c W[o,c] * X[c,n] ----------------
// grid: (32 col-tiles of 128 pixels, 3 = q/k/v, 4 = batch), 256 threads.
// Tile 128(O) x 128(N), BK=16, per-thread 8(O) x 8(N) with cols at 32j + 2tc
// (conflict-free LDS.64 on the B fragment).
__global__ __launch_bounds__(256) void qkv_gemm(
    const float* __restrict__ x,
    const float* __restrict__ wq,
    const float* __restrict__ wk,
    const float* __restrict__ wv)
{
    const int nTile = blockIdx.x * 128;
    const int which = blockIdx.y;
    const int b     = blockIdx.z;

    const float* Wt = (which == 0) ? wq : (which == 1) ? wk : wv;

    __shared__ float As[16][132];   // [k][o]
    __shared__ float Bs[16][132];   // [k][n]

    const int t  = threadIdx.x;
    const int tr = t >> 4;          // 0..15
    const int tc = t & 15;          // 0..15

    ull acc2[8][4];
    #pragma unroll
    for (int i = 0; i < 8; i++)
        #pragma unroll
        for (int j = 0; j < 4; j++) acc2[i][j] = 0ull;

    const float* Xb = x + (size_t)b * C_ * HW_ + nTile;

    for (int k0 = 0; k0 < C_; k0 += 16) {
        #pragma unroll
        for (int i = 0; i < 2; i++) {
            int f   = t + i * 256;
            int row = f >> 2;
            int cv  = f & 3;
            float4 a = *reinterpret_cast<const float4*>(&Wt[row * C_ + k0 + cv * 4]);
            As[cv * 4 + 0][row] = a.x;
            As[cv * 4 + 1][row] = a.y;
            As[cv * 4 + 2][row] = a.z;
            As[cv * 4 + 3][row] = a.w;
        }
        #pragma unroll
        for (int i = 0; i < 2; i++) {
            int f   = t + i * 256;
            int row = f >> 5;
            int cv  = f & 31;
            float4 v = *reinterpret_cast<const float4*>(&Xb[(size_t)(k0 + row) * HW_ + cv * 4]);
            *reinterpret_cast<float4*>(&Bs[row][cv * 4]) = v;
        }
        __syncthreads();

        #pragma unroll
        for (int k = 0; k < 16; k++) {
            float a[8];
            #pragma unroll
            for (int i = 0; i < 8; i++) a[i] = As[k][tr * 8 + i];
            ull b2[4];
            #pragma unroll
            for (int j = 0; j < 4; j++)
                b2[j] = *reinterpret_cast<const ull*>(&Bs[k][32 * j + 2 * tc]);
            #pragma unroll
            for (int i = 0; i < 8; i++) {
                ull aa = pack2(a[i], a[i]);
                #pragma unroll
                for (int j = 0; j < 4; j++)
                    acc2[i][j] = fma2(aa, b2[j], acc2[i][j]);
            }
        }
        __syncthreads();
    }

    if (which == 0) {
        float* Ob = g_q + (size_t)b * O_ * HW_ + nTile;
        #pragma unroll
        for (int i = 0; i < 8; i++) {
            int o = tr * 8 + i;
            #pragma unroll
            for (int j = 0; j < 4; j++) {
                float2 v = unpack2(acc2[i][j]);
                *reinterpret_cast<float2*>(&Ob[(size_t)o * HW_ + 32 * j + 2 * tc]) = v;
            }
        }
    } else {
        float* dst0 = (which == 1) ? g_kp : g_vp;
        #pragma unroll
        for (int i = 0; i < 8; i++) {
            int o = tr * 8 + i;
            float* base = dst0 + (size_t)(b * O_ + o) * CHP_;
            #pragma unroll
            for (int j = 0; j < 4; j++) {
                int p   = nTile + 32 * j + 2 * tc;
                int row = p >> 6;
                int col = p & 63;
                float2 v = unpack2(acc2[i][j]);
                float* d = base + (row + PAD_) * PCOLS_ + (col + PAD_);
                d[0] = v.x;
                d[1] = v.y;
            }
        }
    }
}

// ---------------- Attention ----------------
// Block = 128 threads = 16 pixel-pairs (half a row, 32 px) x 8 channel-lanes.
// Grid = (128 = 64 rows x 2 halves, 4 batches) = 512 blocks.
// Channels in 8 chunks of 16; lane ln owns channels {2ln, 2ln+1} of each chunk.
// Logits packed f32x2 over the pixel pair; lane reduce via 3x shfl_xor.
#define WS_ 290    // smem channel stride (>= 7*40, == 2 mod 16 for bank spread)

__device__ __forceinline__ void load_window(
    const float* __restrict__ src, int bc0, int h, int half, int t, float* sW)
{
    const float* base = src + (size_t)bc0 * CHP_ + (size_t)h * PCOLS_ + half * 32;
    #pragma unroll
    for (int i = 0; i < 9; i++) {
        int lin = t + i * 128;            // over 16ch * 7rows * 10 float4 = 1120
        if (lin < 1120) {
            int c   = lin / 70;
            int rem = lin - c * 70;
            int row = rem / 10;
            int c4  = rem - row * 10;
            float4 v = *reinterpret_cast<const float4*>(
                base + (size_t)c * CHP_ + row * PCOLS_ + c4 * 4);
            float* d = sW + c * WS_ + row * 40 + c4 * 4;
            *reinterpret_cast<float2*>(d)     = make_float2(v.x, v.y);
            *reinterpret_cast<float2*>(d + 2) = make_float2(v.z, v.w);
        }
    }
}

__global__ __launch_bounds__(128, 3) void attn_kernel(
    const float* __restrict__ rel_x,
    const float* __restrict__ rel_y,
    float* __restrict__ out)
{
    const int hb   = blockIdx.x;       // 0..127
    const int h    = hb >> 1;
    const int half = hb & 1;
    const int b    = blockIdx.y;
    const int t    = threadIdx.x;
    const int ln   = t & 7;            // channel lane
    const int pp   = t >> 3;           // pixel pair 0..15

    __shared__ float sW[16 * WS_];
    __shared__ float sQ[16][32];
    __shared__ float sR[16][7];

    if (t < 112) {
        int r = t / 7;
        sR[r][t - r * 7] = (r < 8) ? rel_x[t] : rel_y[t - 56];
    }

    ull logits[49];
    #pragma unroll
    for (int i = 0; i < 49; i++) logits[i] = 0ull;
    ull bias[7] = {0ull, 0ull, 0ull, 0ull, 0ull, 0ull, 0ull};

    const int cl0 = 2 * ln;            // local channels cl0, cl0+1

    // ---------------- Phase 1: logits + bias partials ----------------
    for (int cc = 0; cc < 8; cc++) {
        const int c0 = cc * 16;
        __syncthreads();
        load_window(g_kp, b * O_ + c0, h, half, t, sW);
        {
            int c = t >> 3, c4 = t & 7;
            *reinterpret_cast<float4*>(&sQ[c][c4 * 4]) =
                *reinterpret_cast<const float4*>(
                    &g_q[(size_t)(b * O_ + c0 + c) * HW_ + h * W_ + half * 32 + c4 * 4]);
        }
        __syncthreads();

        #pragma unroll
        for (int sub = 0; sub < 2; sub++) {
            const int c = cl0 + sub;
            const ull q2 = *reinterpret_cast<const ull*>(&sQ[c][2 * pp]);
            #pragma unroll
            for (int k = 0; k < 7; k++) {
                float rv = sR[c][k];
                bias[k] = fma2(q2, pack2(rv, rv), bias[k]);
            }
            const float* wp = &sW[c * WS_ + 2 * pp];
            #pragma unroll
            for (int ki = 0; ki < 7; ki++) {
                const ull* rp = reinterpret_cast<const ull*>(wp + ki * 40);
                ull v0 = rp[0], v1 = rp[1], v2 = rp[2], v3 = rp[3];
                ull p1 = mix_hl(v0, v1);
                ull p3 = mix_hl(v1, v2);
                ull p5 = mix_hl(v2, v3);
                logits[ki * 7 + 0] = fma2(q2, v0, logits[ki * 7 + 0]);
                logits[ki * 7 + 1] = fma2(q2, p1, logits[ki * 7 + 1]);
                logits[ki * 7 + 2] = fma2(q2, v1, logits[ki * 7 + 2]);
                logits[ki * 7 + 3] = fma2(q2, p3, logits[ki * 7 + 3]);
                logits[ki * 7 + 4] = fma2(q2, v2, logits[ki * 7 + 4]);
                logits[ki * 7 + 5] = fma2(q2, p5, logits[ki * 7 + 5]);
                logits[ki * 7 + 6] = fma2(q2, v3, logits[ki * 7 + 6]);
            }
        }
    }

    // Fold bias partials into logits pre-reduction: lanes 0..3 hold bias_x
    // partials (index kj), lanes 4..7 hold bias_y partials (index ki). The
    // lane reduction then yields logits + bias_x[kj] + bias_y[ki].
    if (ln < 4) {
        #pragma unroll
        for (int ki = 0; ki < 7; ki++)
            #pragma unroll
            for (int kj = 0; kj < 7; kj++)
                logits[ki * 7 + kj] = add2(logits[ki * 7 + kj], bias[kj]);
    } else {
        #pragma unroll
        for (int ki = 0; ki < 7; ki++)
            #pragma unroll
            for (int kj = 0; kj < 7; kj++)
                logits[ki * 7 + kj] = add2(logits[ki * 7 + kj], bias[ki]);
    }

    // Reduce over the 8 channel lanes (warp lane bits 0..2).
    const unsigned mask = 0xFFFFFFFFu;
    #pragma unroll
    for (int i = 0; i < 49; i++) {
        ull v = logits[i];
        v = add2(v, __shfl_xor_sync(mask, v, 1));
        v = add2(v, __shfl_xor_sync(mask, v, 2));
        v = add2(v, __shfl_xor_sync(mask, v, 4));
        logits[i] = v;
    }

    // ---------------- Softmax (both pixels of the pair) ----------------
    float m0 = -3.0e38f, m1 = -3.0e38f;
    #pragma unroll
    for (int i = 0; i < 49; i++) {
        float2 f = unpack2(logits[i]);
        m0 = fmaxf(m0, f.x);
        m1 = fmaxf(m1, f.y);
    }
    float s0 = 0.f, s1 = 0.f;
    #pragma unroll
    for (int i = 0; i < 49; i++) {
        float2 f = unpack2(logits[i]);
        float e0 = __expf(f.x - m0);
        float e1 = __expf(f.y - m1);
        s0 += e0; s1 += e1;
        logits[i] = pack2(e0, e1);
    }
    const ull inv2 = pack2(1.f / s0, 1.f / s1);
    #pragma unroll
    for (int i = 0; i < 49; i++) logits[i] = mul2(logits[i], inv2);

    // ---------------- Phase 2: out = attn . v_window ----------------
    for (int cc = 0; cc < 8; cc++) {
        const int c0 = cc * 16;
        __syncthreads();
        load_window(g_vp, b * O_ + c0, h, half, t, sW);
        __syncthreads();

        #pragma unroll
        for (int sub = 0; sub < 2; sub++) {
            const int c = cl0 + sub;
            ull acc = 0ull;
            const float* wp = &sW[c * WS_ + 2 * pp];
            #pragma unroll
            for (int ki = 0; ki < 7; ki++) {
                const ull* rp = reinterpret_cast<const ull*>(wp + ki * 40);
                ull v0 = rp[0], v1 = rp[1], v2 = rp[2], v3 = rp[3];
                ull p1 = mix_hl(v0, v1);
                ull p3 = mix_hl(v1, v2);
                ull p5 = mix_hl(v2, v3);
                acc = fma2(logits[ki * 7 + 0], v0, acc);
                acc = fma2(logits[ki * 7 + 1], p1, acc);
                acc = fma2(logits[ki * 7 + 2], v1, acc);
                acc = fma2(logits[ki * 7 + 3], p3, acc);
                acc = fma2(logits[ki * 7 + 4], v2, acc);
                acc = fma2(logits[ki * 7 + 5], p5, acc);
                acc = fma2(logits[ki * 7 + 6], v3, acc);
            }
            float2 r = unpack2(acc);
            *reinterpret_cast<float2*>(
                &out[(size_t)(b * O_ + c0 + c) * HW_ + h * W_ + half * 32 + 2 * pp]) = r;
        }
    }
}

// ---------------- launch ----------------
extern "C" void kernel_launch(void* const* d_in, const int* in_sizes, int n_in,
                              void* d_out, int out_size) {
    (void)in_sizes; (void)n_in; (void)out_size;
    const float* x     = (const float*)d_in[0];
    const float* wq    = (const float*)d_in[1];
    const float* wk    = (const float*)d_in[2];
    const float* wv    = (const float*)d_in[3];
    const float* rel_x = (const float*)d_in[4];
    const float* rel_y = (const float*)d_in[5];
    float* out = (float*)d_out;

    zero_pads<<<(2 * B_ * O_ * PROWS_ + 255) / 256, 256>>>();
    qkv_gemm<<<dim3(32, 3, 4), 256>>>(x, wq, wk, wv);
    attn_kernel<<<dim3(128, 4), 128>>>(rel_x, rel_y, out);
}